// round 5
// baseline (speedup 1.0000x reference)
#include <cuda_runtime.h>
#include <cstdint>

#define DIM      64
#define TILE_M   128
#define THREADS  128

// ---- shared memory: A hi/lo tiles (SW128) + per-row norm^2 ----
#define SM_A_HI  0
#define SM_A_LO  (SM_A_HI + TILE_M * 128)     // 16 KB each
#define SM_N2    (SM_A_LO + TILE_M * 128)
#define SM_TOTAL (SM_N2 + TILE_M * 4)         // 33280 B

// precomputed rho B-fragments: [kk][nblock j][lane] -> (b0,b1) bf16x2 pairs
__device__ uint2 g_bh[4][8][32];
__device__ uint2 g_bl[4][8][32];

static __device__ __forceinline__ uint32_t smem_u32(const void* p) {
    uint32_t a;
    asm("{ .reg .u64 t; cvta.to.shared.u64 t, %1; cvt.u32.u64 %0, t; }"
        : "=r"(a) : "l"(p));
    return a;
}

static __device__ __forceinline__ uint32_t sw128(uint32_t off) {
    return off ^ ((off >> 3) & 0x70u);
}

// pack two fp32 -> bf16x2 (a low half, b high half) + residual pair
static __device__ __forceinline__ void split_pair(float a, float b,
                                                  uint32_t& hi, uint32_t& lo) {
    uint32_t h;
    asm("cvt.rn.bf16x2.f32 %0, %1, %2;" : "=r"(h) : "f"(b), "f"(a));
    float ha = __uint_as_float(h << 16);
    float hb = __uint_as_float(h & 0xFFFF0000u);
    uint32_t l;
    float la = a - ha, lb = b - hb;
    asm("cvt.rn.bf16x2.f32 %0, %1, %2;" : "=r"(l) : "f"(lb), "f"(la));
    hi = h; lo = l;
}

static __device__ __forceinline__ void ldsm4(uint32_t* r, uint32_t addr) {
    asm volatile("ldmatrix.sync.aligned.m8n8.x4.shared.b16 {%0,%1,%2,%3}, [%4];"
                 : "=r"(r[0]), "=r"(r[1]), "=r"(r[2]), "=r"(r[3]) : "r"(addr));
}

static __device__ __forceinline__ void mma_bf16(float* d, const uint32_t* a,
                                                uint32_t b0, uint32_t b1) {
    asm volatile(
        "mma.sync.aligned.m16n8k16.row.col.f32.bf16.bf16.f32 "
        "{%0,%1,%2,%3}, {%4,%5,%6,%7}, {%8,%9}, {%0,%1,%2,%3};"
        : "+f"(d[0]), "+f"(d[1]), "+f"(d[2]), "+f"(d[3])
        : "r"(a[0]), "r"(a[1]), "r"(a[2]), "r"(a[3]), "r"(b0), "r"(b1));
}

// ---- setup: split rho into B-fragment-layout hi/lo tables (runs once) ----
__global__ void rho_split_kernel(const float* __restrict__ rho) {
    const int t = blockIdx.x * blockDim.x + threadIdx.x;   // 0..1023
    const int lane = t & 31;
    const int j    = (t >> 5) & 7;
    const int kk   = t >> 8;
    const int n  = j * 8 + (lane >> 2);
    const int k0 = kk * 16 + (lane & 3) * 2;
    const float v0 = rho[n * DIM + k0],     v1 = rho[n * DIM + k0 + 1];
    const float v2 = rho[n * DIM + k0 + 8], v3 = rho[n * DIM + k0 + 9];
    uint32_t h0, l0, h1, l1;
    split_pair(v0, v1, h0, l0);
    split_pair(v2, v3, h1, l1);
    g_bh[kk][j][lane] = make_uint2(h0, h1);
    g_bl[kk][j][lane] = make_uint2(l0, l1);
}

__global__ void __launch_bounds__(THREADS, 4)
qmeas_kernel(const float* __restrict__ x, float* __restrict__ out, int nrows) {
    extern __shared__ char smem[];
    const uint32_t sb = smem_u32(smem);
    float* n2s = (float*)(smem + SM_N2);

    const int tid  = threadIdx.x;
    const int lane = tid & 31;
    const int wid  = tid >> 5;

    const long blkbase = (long)blockIdx.x * TILE_M;
    const long row = blkbase + tid;
    const bool valid = (row < (long)nrows);

    // ---- load my x row (fp32), norm^2, split into bf16 hi/lo SW128 tiles ----
    {
        float xv[DIM];
        float norm2 = 0.f;
        if (valid) {
            const float4* xp = (const float4*)(x + (size_t)row * DIM);
            #pragma unroll
            for (int i = 0; i < DIM / 4; i++) {
                float4 v = xp[i];
                xv[4*i+0] = v.x; xv[4*i+1] = v.y; xv[4*i+2] = v.z; xv[4*i+3] = v.w;
                norm2 += v.x*v.x + v.y*v.y + v.z*v.z + v.w*v.w;
            }
        } else {
            #pragma unroll
            for (int i = 0; i < DIM; i++) xv[i] = 0.f;
        }
        n2s[tid] = norm2;

        #pragma unroll
        for (int c = 0; c < 8; c++) {
            uint32_t hi[4], lo[4];
            #pragma unroll
            for (int p = 0; p < 4; p++)
                split_pair(xv[c*8 + 2*p], xv[c*8 + 2*p + 1], hi[p], lo[p]);
            uint32_t off = sw128((uint32_t)tid * 128u + (uint32_t)c * 16u);
            asm volatile("st.shared.v4.b32 [%0], {%1,%2,%3,%4};"
                         :: "r"(sb + SM_A_HI + off), "r"(hi[0]), "r"(hi[1]), "r"(hi[2]), "r"(hi[3])
                         : "memory");
            asm volatile("st.shared.v4.b32 [%0], {%1,%2,%3,%4};"
                         :: "r"(sb + SM_A_LO + off), "r"(lo[0]), "r"(lo[1]), "r"(lo[2]), "r"(lo[3])
                         : "memory");
        }
    }
    __syncthreads();

    // ---- GEMM1: Y[128,64] = X * rho^T (3-term bf16 split), rho frags via LDG
    const int mbase = wid * 32;
    const int lane7 = lane & 7;
    const int agrp  = lane >> 3;
    const uint32_t kA = (uint32_t)((agrp >> 1) * 16);
    uint32_t arow[2];
    #pragma unroll
    for (int t = 0; t < 2; t++)
        arow[t] = (uint32_t)(mbase + t*16 + (agrp & 1)*8 + lane7) * 128u;

    float acc[2][8][4];
    #pragma unroll
    for (int t = 0; t < 2; t++)
        #pragma unroll
        for (int j = 0; j < 8; j++)
            #pragma unroll
            for (int q = 0; q < 4; q++) acc[t][j][q] = 0.f;

    #pragma unroll
    for (int kk = 0; kk < 4; kk++) {
        const uint32_t kb = (uint32_t)(kk * 32);
        uint32_t ah[2][4], al[2][4];
        #pragma unroll
        for (int t = 0; t < 2; t++) {
            uint32_t off = sw128(arow[t] + kb + kA);
            ldsm4(ah[t], sb + SM_A_HI + off);
            ldsm4(al[t], sb + SM_A_LO + off);
        }
        uint2 bh[8];
        #pragma unroll
        for (int j = 0; j < 8; j++) bh[j] = g_bh[kk][j][lane];
        #pragma unroll
        for (int j = 0; j < 8; j++) {
            mma_bf16(acc[0][j], ah[0], bh[j].x, bh[j].y);
            mma_bf16(acc[1][j], ah[1], bh[j].x, bh[j].y);
            mma_bf16(acc[0][j], al[0], bh[j].x, bh[j].y);
            mma_bf16(acc[1][j], al[1], bh[j].x, bh[j].y);
        }
        uint2 bl[8];
        #pragma unroll
        for (int j = 0; j < 8; j++) bl[j] = g_bl[kk][j][lane];
        #pragma unroll
        for (int j = 0; j < 8; j++) {
            mma_bf16(acc[0][j], ah[0], bl[j].x, bl[j].y);
            mma_bf16(acc[1][j], ah[1], bl[j].x, bl[j].y);
        }
    }

    // ---- GEMM2: diag(Y X^T) per 16-row tile; A = y (from acc, converted),
    //      B = x fragments reloaded via ldsm (f0,f2 -> s=0; f1,f3 -> s=1)
    float acc2[2][2][4];
    #pragma unroll
    for (int t = 0; t < 2; t++)
        #pragma unroll
        for (int s = 0; s < 2; s++)
            #pragma unroll
            for (int q = 0; q < 4; q++) acc2[t][s][q] = 0.f;

    #pragma unroll
    for (int t = 0; t < 2; t++) {
        #pragma unroll
        for (int kk = 0; kk < 4; kk++) {
            uint32_t yh[4], yl[4];
            split_pair(acc[t][2*kk  ][0], acc[t][2*kk  ][1], yh[0], yl[0]);
            split_pair(acc[t][2*kk  ][2], acc[t][2*kk  ][3], yh[1], yl[1]);
            split_pair(acc[t][2*kk+1][0], acc[t][2*kk+1][1], yh[2], yl[2]);
            split_pair(acc[t][2*kk+1][2], acc[t][2*kk+1][3], yh[3], yl[3]);

            uint32_t fh[4], fl[4];
            uint32_t off = sw128(arow[t] + (uint32_t)(kk * 32) + kA);
            ldsm4(fh, sb + SM_A_HI + off);
            ldsm4(fl, sb + SM_A_LO + off);

            // s = 0 (x rows [16t, 16t+8))
            mma_bf16(acc2[t][0], yh, fh[0], fh[2]);
            mma_bf16(acc2[t][0], yl, fh[0], fh[2]);
            mma_bf16(acc2[t][0], yh, fl[0], fl[2]);
            // s = 1 (x rows [16t+8, 16t+16))
            mma_bf16(acc2[t][1], yh, fh[1], fh[3]);
            mma_bf16(acc2[t][1], yl, fh[1], fh[3]);
            mma_bf16(acc2[t][1], yh, fl[1], fl[3]);
        }
    }

    // ---- diag extraction + write: each row's dot sits in exactly one lane/reg
    const int r0 = lane >> 2;
    const int cq = (lane & 3) * 2;
    const bool e0 = (r0 == cq);
    const bool e1 = (r0 == cq + 1);
    #pragma unroll
    for (int t = 0; t < 2; t++) {
        const int lr = mbase + 16*t + r0;
        const long g0 = blkbase + lr;       // s=0 rows (c0/c1, row r0)
        const long g1 = g0 + 8;             // s=1 rows (c2/c3, row r0+8)
        if (e0 && g0 < (long)nrows) out[g0] = n2s[lr]     * acc2[t][0][0];
        if (e1 && g0 < (long)nrows) out[g0] = n2s[lr]     * acc2[t][0][1];
        if (e0 && g1 < (long)nrows) out[g1] = n2s[lr + 8] * acc2[t][1][2];
        if (e1 && g1 < (long)nrows) out[g1] = n2s[lr + 8] * acc2[t][1][3];
    }
}

extern "C" void kernel_launch(void* const* d_in, const int* in_sizes, int n_in,
                              void* d_out, int out_size) {
    const float* x   = (const float*)d_in[0];
    const float* rho = (const float*)d_in[1];
    float* out = (float*)d_out;
    const int nrows = out_size;

    cudaFuncSetAttribute(qmeas_kernel,
                         cudaFuncAttributeMaxDynamicSharedMemorySize, SM_TOTAL);

    rho_split_kernel<<<4, 256>>>(rho);
    const int grid = (nrows + TILE_M - 1) / TILE_M;
    qmeas_kernel<<<grid, THREADS, SM_TOTAL>>>(x, out, nrows);
}

// round 7
// speedup vs baseline: 1.1401x; 1.1401x over previous
#include <cuda_runtime.h>
#include <cstdint>

#define DIM      64
#define TILE_M   128
#define THREADS  256

// ---- shared memory: A hi/lo tiles (SW128) + per-row norm^2 ----
#define SM_A_HI  0
#define SM_A_LO  (SM_A_HI + TILE_M * 128)     // 16 KB each
#define SM_N2    (SM_A_LO + TILE_M * 128)
#define SM_TOTAL (SM_N2 + TILE_M * 4)         // 33280 B

// precomputed rho B-fragments: [kk][nblock j][lane] -> (b0,b1) bf16x2 pairs
__device__ uint2 g_bh[4][8][32];
__device__ uint2 g_bl[4][8][32];

static __device__ __forceinline__ uint32_t smem_u32(const void* p) {
    uint32_t a;
    asm("{ .reg .u64 t; cvta.to.shared.u64 t, %1; cvt.u32.u64 %0, t; }"
        : "=r"(a) : "l"(p));
    return a;
}

static __device__ __forceinline__ uint32_t sw128(uint32_t off) {
    return off ^ ((off >> 3) & 0x70u);
}

// pack two fp32 -> bf16x2 (a low half, b high half) + residual pair
static __device__ __forceinline__ void split_pair(float a, float b,
                                                  uint32_t& hi, uint32_t& lo) {
    uint32_t h;
    asm("cvt.rn.bf16x2.f32 %0, %1, %2;" : "=r"(h) : "f"(b), "f"(a));
    float ha = __uint_as_float(h << 16);
    float hb = __uint_as_float(h & 0xFFFF0000u);
    uint32_t l;
    float la = a - ha, lb = b - hb;
    asm("cvt.rn.bf16x2.f32 %0, %1, %2;" : "=r"(l) : "f"(lb), "f"(la));
    hi = h; lo = l;
}

static __device__ __forceinline__ void ldsm4(uint32_t* r, uint32_t addr) {
    asm volatile("ldmatrix.sync.aligned.m8n8.x4.shared.b16 {%0,%1,%2,%3}, [%4];"
                 : "=r"(r[0]), "=r"(r[1]), "=r"(r[2]), "=r"(r[3]) : "r"(addr));
}

static __device__ __forceinline__ void mma_bf16(float* d, const uint32_t* a,
                                                uint32_t b0, uint32_t b1) {
    asm volatile(
        "mma.sync.aligned.m16n8k16.row.col.f32.bf16.bf16.f32 "
        "{%0,%1,%2,%3}, {%4,%5,%6,%7}, {%8,%9}, {%0,%1,%2,%3};"
        : "+f"(d[0]), "+f"(d[1]), "+f"(d[2]), "+f"(d[3])
        : "r"(a[0]), "r"(a[1]), "r"(a[2]), "r"(a[3]), "r"(b0), "r"(b1));
}

// ---- setup: split rho into B-fragment-layout hi/lo tables (runs once) ----
__global__ void rho_split_kernel(const float* __restrict__ rho) {
    const int t = blockIdx.x * blockDim.x + threadIdx.x;   // 0..1023
    const int lane = t & 31;
    const int j    = (t >> 5) & 7;
    const int kk   = t >> 8;
    const int n  = j * 8 + (lane >> 2);
    const int k0 = kk * 16 + (lane & 3) * 2;
    const float v0 = rho[n * DIM + k0],     v1 = rho[n * DIM + k0 + 1];
    const float v2 = rho[n * DIM + k0 + 8], v3 = rho[n * DIM + k0 + 9];
    uint32_t h0, l0, h1, l1;
    split_pair(v0, v1, h0, l0);
    split_pair(v2, v3, h1, l1);
    g_bh[kk][j][lane] = make_uint2(h0, h1);
    g_bl[kk][j][lane] = make_uint2(l0, l1);
}

__global__ void __launch_bounds__(THREADS, 3)
qmeas_kernel(const float* __restrict__ x, float* __restrict__ out, int nrows) {
    extern __shared__ char smem[];
    const uint32_t sb = smem_u32(smem);
    float* n2s = (float*)(smem + SM_N2);

    const int tid  = threadIdx.x;
    const int lane = tid & 31;
    const int wid  = tid >> 5;              // 0..7, warp owns 16 rows

    const long blkbase = (long)blockIdx.x * TILE_M;

    // ---- load half an x row per thread (fp32), norm^2, split -> SW128 tiles
    {
        const int r  = tid >> 1;            // 0..127 local row
        const int cb = (tid & 1) * 32;      // column base
        const long grow = blkbase + r;
        float xv[32];
        float norm2 = 0.f;
        if (grow < (long)nrows) {
            const float4* xp = (const float4*)(x + (size_t)grow * DIM + cb);
            #pragma unroll
            for (int i = 0; i < 8; i++) {
                float4 v = xp[i];
                xv[4*i+0] = v.x; xv[4*i+1] = v.y; xv[4*i+2] = v.z; xv[4*i+3] = v.w;
                norm2 += v.x*v.x + v.y*v.y + v.z*v.z + v.w*v.w;
            }
        } else {
            #pragma unroll
            for (int i = 0; i < 32; i++) xv[i] = 0.f;
        }
        norm2 += __shfl_xor_sync(0xFFFFFFFFu, norm2, 1);
        if ((tid & 1) == 0) n2s[r] = norm2;

        #pragma unroll
        for (int c = 0; c < 4; c++) {
            uint32_t hi[4], lo[4];
            #pragma unroll
            for (int p = 0; p < 4; p++)
                split_pair(xv[c*8 + 2*p], xv[c*8 + 2*p + 1], hi[p], lo[p]);
            uint32_t off = sw128((uint32_t)r * 128u + (uint32_t)(cb * 2 + c * 16));
            asm volatile("st.shared.v4.b32 [%0], {%1,%2,%3,%4};"
                         :: "r"(sb + SM_A_HI + off), "r"(hi[0]), "r"(hi[1]), "r"(hi[2]), "r"(hi[3])
                         : "memory");
            asm volatile("st.shared.v4.b32 [%0], {%1,%2,%3,%4};"
                         :: "r"(sb + SM_A_LO + off), "r"(lo[0]), "r"(lo[1]), "r"(lo[2]), "r"(lo[3])
                         : "memory");
        }
    }
    __syncthreads();

    // ---- GEMM1: Y[16,64] per warp = X_tile * rho^T (3-term bf16 split) ----
    const int mbase = wid * 16;
    const int lane7 = lane & 7;
    const int agrp  = lane >> 3;
    const uint32_t kA = (uint32_t)((agrp >> 1) * 16);
    const uint32_t arow = (uint32_t)(mbase + (agrp & 1) * 8 + lane7) * 128u;

    float acc[8][4];
    #pragma unroll
    for (int j = 0; j < 8; j++)
        #pragma unroll
        for (int q = 0; q < 4; q++) acc[j][q] = 0.f;

    #pragma unroll
    for (int kk = 0; kk < 4; kk++) {
        const uint32_t off = sw128(arow + (uint32_t)(kk * 32) + kA);
        uint32_t ah[4], al[4];
        ldsm4(ah, sb + SM_A_HI + off);
        ldsm4(al, sb + SM_A_LO + off);
        uint2 bh[8];
        #pragma unroll
        for (int j = 0; j < 8; j++) bh[j] = g_bh[kk][j][lane];
        #pragma unroll
        for (int j = 0; j < 8; j++) {
            mma_bf16(acc[j], ah, bh[j].x, bh[j].y);
            mma_bf16(acc[j], al, bh[j].x, bh[j].y);
        }
        uint2 bl[8];
        #pragma unroll
        for (int j = 0; j < 8; j++) bl[j] = g_bl[kk][j][lane];
        #pragma unroll
        for (int j = 0; j < 8; j++)
            mma_bf16(acc[j], ah, bl[j].x, bl[j].y);
    }

    // ---- GEMM2: diag(Y X^T); A = y (converted in regs), B = x frags (ldsm)
    float acc2[2][4];
    #pragma unroll
    for (int s = 0; s < 2; s++)
        #pragma unroll
        for (int q = 0; q < 4; q++) acc2[s][q] = 0.f;

    #pragma unroll
    for (int kk = 0; kk < 4; kk++) {
        uint32_t yh[4], yl[4];
        split_pair(acc[2*kk  ][0], acc[2*kk  ][1], yh[0], yl[0]);
        split_pair(acc[2*kk  ][2], acc[2*kk  ][3], yh[1], yl[1]);
        split_pair(acc[2*kk+1][0], acc[2*kk+1][1], yh[2], yl[2]);
        split_pair(acc[2*kk+1][2], acc[2*kk+1][3], yh[3], yl[3]);

        const uint32_t off = sw128(arow + (uint32_t)(kk * 32) + kA);
        uint32_t fh[4], fl[4];
        ldsm4(fh, sb + SM_A_HI + off);
        ldsm4(fl, sb + SM_A_LO + off);

        // s = 0 (rows [mbase, mbase+8))
        mma_bf16(acc2[0], yh, fh[0], fh[2]);
        mma_bf16(acc2[0], yl, fh[0], fh[2]);
        mma_bf16(acc2[0], yh, fl[0], fl[2]);
        // s = 1 (rows [mbase+8, mbase+16))
        mma_bf16(acc2[1], yh, fh[1], fh[3]);
        mma_bf16(acc2[1], yl, fh[1], fh[3]);
        mma_bf16(acc2[1], yh, fl[1], fl[3]);
    }

    // ---- diag extraction + write ----
    const int r0 = lane >> 2;
    const int cq = (lane & 3) * 2;
    const bool e0 = (r0 == cq);
    const bool e1 = (r0 == cq + 1);
    const int lr = mbase + r0;
    const long g0 = blkbase + lr;           // s=0 row
    const long g1 = g0 + 8;                 // s=1 row
    if (e0 && g0 < (long)nrows) out[g0] = n2s[lr]     * acc2[0][0];
    if (e1 && g0 < (long)nrows) out[g0] = n2s[lr]     * acc2[0][1];
    if (e0 && g1 < (long)nrows) out[g1] = n2s[lr + 8] * acc2[1][2];
    if (e1 && g1 < (long)nrows) out[g1] = n2s[lr + 8] * acc2[1][3];
}

extern "C" void kernel_launch(void* const* d_in, const int* in_sizes, int n_in,
                              void* d_out, int out_size) {
    const float* x   = (const float*)d_in[0];
    const float* rho = (const float*)d_in[1];
    float* out = (float*)d_out;
    const int nrows = out_size;

    cudaFuncSetAttribute(qmeas_kernel,
                         cudaFuncAttributeMaxDynamicSharedMemorySize, SM_TOTAL);

    rho_split_kernel<<<4, 256>>>(rho);
    const int grid = (nrows + TILE_M - 1) / TILE_M;
    qmeas_kernel<<<grid, THREADS, SM_TOTAL>>>(x, out, nrows);
}

// round 8
// speedup vs baseline: 1.1444x; 1.0038x over previous
#include <cuda_runtime.h>
#include <cstdint>

#define DIM      64
#define TILE_M   128
#define THREADS  256

// ---- shared memory: A hi/lo tiles (SW128) + per-row norm^2 ----
#define SM_A_HI  0
#define SM_A_LO  (SM_A_HI + TILE_M * 128)     // 16 KB each
#define SM_N2    (SM_A_LO + TILE_M * 128)
#define SM_TOTAL (SM_N2 + TILE_M * 4)         // 33280 B

// precomputed rho B-fragments: [kk][nblock j][lane] -> (b0,b1) bf16x2 pairs
__device__ uint2 g_bh[4][8][32];
__device__ uint2 g_bl[4][8][32];

static __device__ __forceinline__ uint32_t smem_u32(const void* p) {
    uint32_t a;
    asm("{ .reg .u64 t; cvta.to.shared.u64 t, %1; cvt.u32.u64 %0, t; }"
        : "=r"(a) : "l"(p));
    return a;
}

static __device__ __forceinline__ uint32_t sw128(uint32_t off) {
    return off ^ ((off >> 3) & 0x70u);
}

// pack two fp32 -> bf16x2 (a low half, b high half) + residual pair
static __device__ __forceinline__ void split_pair(float a, float b,
                                                  uint32_t& hi, uint32_t& lo) {
    uint32_t h;
    asm("cvt.rn.bf16x2.f32 %0, %1, %2;" : "=r"(h) : "f"(b), "f"(a));
    float ha = __uint_as_float(h << 16);
    float hb = __uint_as_float(h & 0xFFFF0000u);
    uint32_t l;
    float la = a - ha, lb = b - hb;
    asm("cvt.rn.bf16x2.f32 %0, %1, %2;" : "=r"(l) : "f"(lb), "f"(la));
    hi = h; lo = l;
}

static __device__ __forceinline__ void ldsm4(uint32_t* r, uint32_t addr) {
    asm volatile("ldmatrix.sync.aligned.m8n8.x4.shared.b16 {%0,%1,%2,%3}, [%4];"
                 : "=r"(r[0]), "=r"(r[1]), "=r"(r[2]), "=r"(r[3]) : "r"(addr));
}

static __device__ __forceinline__ void mma_bf16(float* d, const uint32_t* a,
                                                uint32_t b0, uint32_t b1) {
    asm volatile(
        "mma.sync.aligned.m16n8k16.row.col.f32.bf16.bf16.f32 "
        "{%0,%1,%2,%3}, {%4,%5,%6,%7}, {%8,%9}, {%0,%1,%2,%3};"
        : "+f"(d[0]), "+f"(d[1]), "+f"(d[2]), "+f"(d[3])
        : "r"(a[0]), "r"(a[1]), "r"(a[2]), "r"(a[3]), "r"(b0), "r"(b1));
}

static __device__ __forceinline__ float bf16lo(uint32_t v) {
    return __uint_as_float(v << 16);
}
static __device__ __forceinline__ float bf16hi(uint32_t v) {
    return __uint_as_float(v & 0xFFFF0000u);
}

// ---- setup: split rho into B-fragment-layout hi/lo tables (runs once) ----
__global__ void rho_split_kernel(const float* __restrict__ rho) {
    const int t = blockIdx.x * blockDim.x + threadIdx.x;   // 0..1023
    const int lane = t & 31;
    const int j    = (t >> 5) & 7;
    const int kk   = t >> 8;
    const int n  = j * 8 + (lane >> 2);
    const int k0 = kk * 16 + (lane & 3) * 2;
    const float v0 = rho[n * DIM + k0],     v1 = rho[n * DIM + k0 + 1];
    const float v2 = rho[n * DIM + k0 + 8], v3 = rho[n * DIM + k0 + 9];
    uint32_t h0, l0, h1, l1;
    split_pair(v0, v1, h0, l0);
    split_pair(v2, v3, h1, l1);
    g_bh[kk][j][lane] = make_uint2(h0, h1);
    g_bl[kk][j][lane] = make_uint2(l0, l1);
}

__global__ void __launch_bounds__(THREADS, 3)
qmeas_kernel(const float* __restrict__ x, float* __restrict__ out, int nrows) {
    extern __shared__ char smem[];
    const uint32_t sb = smem_u32(smem);
    float* n2s = (float*)(smem + SM_N2);

    const int tid  = threadIdx.x;
    const int lane = tid & 31;
    const int wid  = tid >> 5;              // 0..7, warp owns 16 rows

    const long blkbase = (long)blockIdx.x * TILE_M;

    // ---- load half an x row per thread (fp32), norm^2, split -> SW128 tiles
    {
        const int r  = tid >> 1;            // 0..127 local row
        const int cb = (tid & 1) * 32;      // column base
        const long grow = blkbase + r;
        float xv[32];
        float norm2 = 0.f;
        if (grow < (long)nrows) {
            const float4* xp = (const float4*)(x + (size_t)grow * DIM + cb);
            #pragma unroll
            for (int i = 0; i < 8; i++) {
                float4 v = xp[i];
                xv[4*i+0] = v.x; xv[4*i+1] = v.y; xv[4*i+2] = v.z; xv[4*i+3] = v.w;
                norm2 += v.x*v.x + v.y*v.y + v.z*v.z + v.w*v.w;
            }
        } else {
            #pragma unroll
            for (int i = 0; i < 32; i++) xv[i] = 0.f;
        }
        norm2 += __shfl_xor_sync(0xFFFFFFFFu, norm2, 1);
        if ((tid & 1) == 0) n2s[r] = norm2;

        #pragma unroll
        for (int c = 0; c < 4; c++) {
            uint32_t hi[4], lo[4];
            #pragma unroll
            for (int p = 0; p < 4; p++)
                split_pair(xv[c*8 + 2*p], xv[c*8 + 2*p + 1], hi[p], lo[p]);
            uint32_t off = sw128((uint32_t)r * 128u + (uint32_t)(cb * 2 + c * 16));
            asm volatile("st.shared.v4.b32 [%0], {%1,%2,%3,%4};"
                         :: "r"(sb + SM_A_HI + off), "r"(hi[0]), "r"(hi[1]), "r"(hi[2]), "r"(hi[3])
                         : "memory");
            asm volatile("st.shared.v4.b32 [%0], {%1,%2,%3,%4};"
                         :: "r"(sb + SM_A_LO + off), "r"(lo[0]), "r"(lo[1]), "r"(lo[2]), "r"(lo[3])
                         : "memory");
        }
    }
    __syncthreads();

    // ---- GEMM1: Y[16,64] per warp = X_tile * rho^T (3-term bf16 split) ----
    const int mbase = wid * 16;
    const int lane7 = lane & 7;
    const int agrp  = lane >> 3;
    const uint32_t kA = (uint32_t)((agrp >> 1) * 16);
    const uint32_t arow = (uint32_t)(mbase + (agrp & 1) * 8 + lane7) * 128u;

    float acc[8][4];
    #pragma unroll
    for (int j = 0; j < 8; j++)
        #pragma unroll
        for (int q = 0; q < 4; q++) acc[j][q] = 0.f;

    #pragma unroll
    for (int kk = 0; kk < 4; kk++) {
        const uint32_t off = sw128(arow + (uint32_t)(kk * 32) + kA);
        uint32_t ah[4], al[4];
        ldsm4(ah, sb + SM_A_HI + off);
        ldsm4(al, sb + SM_A_LO + off);
        uint2 bh[8];
        #pragma unroll
        for (int j = 0; j < 8; j++) bh[j] = g_bh[kk][j][lane];
        #pragma unroll
        for (int j = 0; j < 8; j++) {
            mma_bf16(acc[j], ah, bh[j].x, bh[j].y);
            mma_bf16(acc[j], al, bh[j].x, bh[j].y);
        }
        uint2 bl[8];
        #pragma unroll
        for (int j = 0; j < 8; j++) bl[j] = g_bl[kk][j][lane];
        #pragma unroll
        for (int j = 0; j < 8; j++)
            mma_bf16(acc[j], ah, bl[j].x, bl[j].y);
    }

    // ---- epilogue: dot(x_row, y_row) in fp32 via FFMA (no GEMM2).
    // C-frag: c0,c1 -> (rowA = mbase+r0, cols 8j+cq, +1); c2,c3 -> rowA+8.
    // x reconstructed as hi+lo from the smem tiles (plain loads so the
    // compiler can schedule them under the MMA tail).
    const int r0 = lane >> 2;
    const int cq = (lane & 3) * 2;
    const int rowA = mbase + r0;
    const int rowB = rowA + 8;
    float dA = 0.f, dB = 0.f;
    #pragma unroll
    for (int j = 0; j < 8; j++) {
        const uint32_t cbyte = (uint32_t)(j * 8 + cq) * 2u;
        const uint32_t offA = sw128((uint32_t)rowA * 128u + cbyte);
        const uint32_t offB = sw128((uint32_t)rowB * 128u + cbyte);
        const uint32_t hA = *(const uint32_t*)(smem + SM_A_HI + offA);
        const uint32_t lA = *(const uint32_t*)(smem + SM_A_LO + offA);
        const uint32_t hB = *(const uint32_t*)(smem + SM_A_HI + offB);
        const uint32_t lB = *(const uint32_t*)(smem + SM_A_LO + offB);
        const float xa0 = bf16lo(hA) + bf16lo(lA);
        const float xa1 = bf16hi(hA) + bf16hi(lA);
        const float xb0 = bf16lo(hB) + bf16lo(lB);
        const float xb1 = bf16hi(hB) + bf16hi(lB);
        dA += xa0 * acc[j][0] + xa1 * acc[j][1];
        dB += xb0 * acc[j][2] + xb1 * acc[j][3];
    }
    // quad-lane reduce: lanes {l, l^1, l^2} cover all 64 columns
    dA += __shfl_xor_sync(0xFFFFFFFFu, dA, 1);
    dA += __shfl_xor_sync(0xFFFFFFFFu, dA, 2);
    dB += __shfl_xor_sync(0xFFFFFFFFu, dB, 1);
    dB += __shfl_xor_sync(0xFFFFFFFFu, dB, 2);

    if ((lane & 3) == 0) {
        const long gA = blkbase + rowA;
        const long gB = blkbase + rowB;
        if (gA < (long)nrows) out[gA] = n2s[rowA] * dA;
        if (gB < (long)nrows) out[gB] = n2s[rowB] * dB;
    }
}

extern "C" void kernel_launch(void* const* d_in, const int* in_sizes, int n_in,
                              void* d_out, int out_size) {
    const float* x   = (const float*)d_in[0];
    const float* rho = (const float*)d_in[1];
    float* out = (float*)d_out;
    const int nrows = out_size;

    cudaFuncSetAttribute(qmeas_kernel,
                         cudaFuncAttributeMaxDynamicSharedMemorySize, SM_TOTAL);

    rho_split_kernel<<<4, 256>>>(rho);
    const int grid = (nrows + TILE_M - 1) / TILE_M;
    qmeas_kernel<<<grid, THREADS, SM_TOTAL>>>(x, out, nrows);
}